// round 2
// baseline (speedup 1.0000x reference)
#include <cuda_runtime.h>
#include <cstdint>

#define BATCH 4096
#define NN 17
#define DIM 512
#define OUTC 3

// Scratch (allocation-free rule: __device__ globals)
__device__ float g_H[(size_t)BATCH * 2 * DIM];   // [B, 1024] = shift | scale
__device__ float g_L[NN * NN];
__device__ float g_Q[NN * NN];                   // Q = 2 L^2 - I

// ---------------------------------------------------------------------------
// Kernel 0: normalized Laplacian L = I - D^{-1/2} A D^{-1/2}, and Q = 2L^2 - I
// ---------------------------------------------------------------------------
__global__ void lap_kernel(const float* __restrict__ adj) {
    __shared__ float sD[NN];
    __shared__ float sL[NN * NN];
    int t = threadIdx.x;
    if (t < NN) {
        float s = 0.f;
        #pragma unroll
        for (int m = 0; m < NN; m++) s += adj[t * NN + m];
        sD[t] = rsqrtf(s);
    }
    __syncthreads();
    if (t < NN * NN) {
        int n = t / NN, m = t % NN;
        float v = ((n == m) ? 1.f : 0.f) - sD[n] * adj[t] * sD[m];
        sL[t] = v;
        g_L[t] = v;
    }
    __syncthreads();
    if (t < NN * NN) {
        int n = t / NN, m = t % NN;
        float s = 0.f;
        #pragma unroll
        for (int j = 0; j < NN; j++) s += sL[n * NN + j] * sL[j * NN + m];
        g_Q[t] = 2.f * s - ((n == m) ? 1.f : 0.f);
    }
}

// ---------------------------------------------------------------------------
// Kernel 1: H[b, :] = silu(c[b,:]) @ W_mod + b_mod      (4096x1024 = 4096x512 @ 512x1024)
// Tiled fp32 GEMM: block tile 64(M) x 128(N), 256 threads, 4x8 micro-tile, KC=16
// ---------------------------------------------------------------------------
#define KC 16
#define TM 64
#define TN 128

__global__ __launch_bounds__(256) void mod_gemm(const float* __restrict__ Cin,
                                                const float* __restrict__ W,
                                                const float* __restrict__ bias) {
    __shared__ float sA[KC][TM];   // sA[k][m] = silu(c[m0+m, k0+k])
    __shared__ float sB[KC][TN];   // sB[k][n] = W[k0+k, n0+n]
    const int tid = threadIdx.x;
    const int m0 = blockIdx.y * TM;
    const int n0 = blockIdx.x * TN;
    const int tx = tid & 15;       // n-dim
    const int ty = tid >> 4;       // m-dim
    const int am = tid >> 2;       // 0..63 : A-load row
    const int ak = (tid & 3) << 2; // 0,4,8,12 : A-load k base

    float acc[4][8];
    #pragma unroll
    for (int i = 0; i < 4; i++)
        #pragma unroll
        for (int j = 0; j < 8; j++) acc[i][j] = 0.f;

    for (int k0 = 0; k0 < DIM; k0 += KC) {
        // --- A tile: load + silu + transpose into sA[k][m] ---
        float4 av = *reinterpret_cast<const float4*>(Cin + (size_t)(m0 + am) * DIM + k0 + ak);
        sA[ak + 0][am] = av.x / (1.f + __expf(-av.x));
        sA[ak + 1][am] = av.y / (1.f + __expf(-av.y));
        sA[ak + 2][am] = av.z / (1.f + __expf(-av.z));
        sA[ak + 3][am] = av.w / (1.f + __expf(-av.w));
        // --- B tile ---
        #pragma unroll
        for (int r = 0; r < 2; r++) {
            int f = tid + r * 256;
            int bk = f >> 5;              // 0..15
            int bn = (f & 31) << 2;       // 0..124
            *reinterpret_cast<float4*>(&sB[bk][bn]) =
                *reinterpret_cast<const float4*>(W + (size_t)(k0 + bk) * (2 * DIM) + n0 + bn);
        }
        __syncthreads();
        #pragma unroll
        for (int k = 0; k < KC; k++) {
            float4 a  = *reinterpret_cast<const float4*>(&sA[k][ty << 2]);
            float4 b0 = *reinterpret_cast<const float4*>(&sB[k][tx << 3]);
            float4 b1 = *reinterpret_cast<const float4*>(&sB[k][(tx << 3) + 4]);
            float aa[4] = {a.x, a.y, a.z, a.w};
            float bb[8] = {b0.x, b0.y, b0.z, b0.w, b1.x, b1.y, b1.z, b1.w};
            #pragma unroll
            for (int i = 0; i < 4; i++)
                #pragma unroll
                for (int j = 0; j < 8; j++) acc[i][j] += aa[i] * bb[j];
        }
        __syncthreads();
    }
    float4 g0 = *reinterpret_cast<const float4*>(bias + n0 + (tx << 3));
    float4 g1 = *reinterpret_cast<const float4*>(bias + n0 + (tx << 3) + 4);
    #pragma unroll
    for (int i = 0; i < 4; i++) {
        float* op = g_H + (size_t)(m0 + (ty << 2) + i) * (2 * DIM) + n0 + (tx << 3);
        float4 o0 = make_float4(acc[i][0] + g0.x, acc[i][1] + g0.y, acc[i][2] + g0.z, acc[i][3] + g0.w);
        float4 o1 = make_float4(acc[i][4] + g1.x, acc[i][5] + g1.y, acc[i][6] + g1.z, acc[i][7] + g1.w);
        *reinterpret_cast<float4*>(op)     = o0;
        *reinterpret_cast<float4*>(op + 4) = o1;
    }
}

// ---------------------------------------------------------------------------
// Kernel 2: per batch element b (one block):
//   LN(x[b]) -> modulate with (shift,scale)=g_H[b] -> y_k = xm @ Wg[k]  (17x3 x3)
//   out[b] = y0 + L y1 + Q y2 + bg
// 192 threads = 6 warps; warp w owns rows {3w, 3w+1, 3w+2} (clamped), so the 9
// Wg smem reads per float4-group are amortized over 3 rows.
// ---------------------------------------------------------------------------
__global__ __launch_bounds__(192) void final_kernel(const float* __restrict__ x,
                                                    const float* __restrict__ Wg,
                                                    const float* __restrict__ bg,
                                                    float* __restrict__ out) {
    __shared__ float sWg[9][DIM];      // [(k*3+o)][c]  (transposed for stride-1 c)
    __shared__ float sMod[2 * DIM];    // shift | scale
    __shared__ float sL[NN * NN];
    __shared__ float sQ[NN * NN];
    __shared__ float sY[3][NN][OUTC];

    const int b = blockIdx.x;
    const int tid = threadIdx.x;
    const int w = tid >> 5;
    const int l = tid & 31;

    for (int i = tid; i < 3 * DIM * OUTC; i += 192) {
        int k = i / (DIM * OUTC);
        int r = i - k * (DIM * OUTC);
        int c = r / OUTC;
        int o = r - c * OUTC;
        sWg[k * 3 + o][c] = Wg[i];
    }
    {
        const float4* hp = reinterpret_cast<const float4*>(g_H + (size_t)b * 2 * DIM);
        float4* mp = reinterpret_cast<float4*>(sMod);
        for (int i = tid; i < (2 * DIM) / 4; i += 192) mp[i] = hp[i];
    }
    for (int i = tid; i < NN * NN; i += 192) { sL[i] = g_L[i]; sQ[i] = g_Q[i]; }
    __syncthreads();

    // --- load x rows + LayerNorm stats (warp-owned rows, lane strides of 4 floats) ---
    float4 xr[3][4];
    float mean[3], rstd[3];
    #pragma unroll
    for (int r = 0; r < 3; r++) {
        int n = w * 3 + r; if (n > NN - 1) n = NN - 1;   // clamp (dup row 16, write guarded)
        const float4* xp = reinterpret_cast<const float4*>(x + ((size_t)b * NN + n) * DIM);
        float s = 0.f, s2 = 0.f;
        #pragma unroll
        for (int j = 0; j < 4; j++) {
            float4 v = xp[j * 32 + l];
            xr[r][j] = v;
            s  += v.x + v.y + v.z + v.w;
            s2 += v.x * v.x + v.y * v.y + v.z * v.z + v.w * v.w;
        }
        #pragma unroll
        for (int off = 16; off; off >>= 1) {
            s  += __shfl_xor_sync(0xffffffffu, s,  off);
            s2 += __shfl_xor_sync(0xffffffffu, s2, off);
        }
        float mu  = s * (1.f / DIM);
        float var = s2 * (1.f / DIM) - mu * mu;
        mean[r] = mu;
        rstd[r] = rsqrtf(var + 1e-6f);
    }

    // --- modulate + project: acc[r][k*3+o] = sum_c xm * Wg ---
    float acc[3][9];
    #pragma unroll
    for (int r = 0; r < 3; r++)
        #pragma unroll
        for (int t = 0; t < 9; t++) acc[r][t] = 0.f;

    const float4* modV = reinterpret_cast<const float4*>(sMod);
    const float4* wgV  = reinterpret_cast<const float4*>(sWg);
    #pragma unroll
    for (int j = 0; j < 4; j++) {
        float4 sh = modV[j * 32 + l];
        float4 sc = modV[128 + j * 32 + l];
        float4 wv[9];
        #pragma unroll
        for (int t = 0; t < 9; t++) wv[t] = wgV[t * 128 + j * 32 + l];
        #pragma unroll
        for (int r = 0; r < 3; r++) {
            float4 v = xr[r][j];
            float4 xm;
            xm.x = (v.x - mean[r]) * rstd[r] * (1.f + sc.x) + sh.x;
            xm.y = (v.y - mean[r]) * rstd[r] * (1.f + sc.y) + sh.y;
            xm.z = (v.z - mean[r]) * rstd[r] * (1.f + sc.z) + sh.z;
            xm.w = (v.w - mean[r]) * rstd[r] * (1.f + sc.w) + sh.w;
            #pragma unroll
            for (int t = 0; t < 9; t++)
                acc[r][t] += xm.x * wv[t].x + xm.y * wv[t].y + xm.z * wv[t].z + xm.w * wv[t].w;
        }
    }

    // --- warp-reduce the 9 projections per row, write to sY ---
    #pragma unroll
    for (int r = 0; r < 3; r++) {
        int n = w * 3 + r;
        #pragma unroll
        for (int t = 0; t < 9; t++) {
            float a = acc[r][t];
            #pragma unroll
            for (int off = 16; off; off >>= 1) a += __shfl_xor_sync(0xffffffffu, a, off);
            if (l == 0 && n < NN) sY[t / 3][n][t % 3] = a;
        }
    }
    __syncthreads();

    // --- graph combine: out = y0 + L y1 + Q y2 + bg ---
    if (tid < NN * OUTC) {
        int n = tid / OUTC, o = tid - n * OUTC;
        float res = sY[0][n][o] + bg[o];
        #pragma unroll
        for (int m = 0; m < NN; m++)
            res += sL[n * NN + m] * sY[1][m][o] + sQ[n * NN + m] * sY[2][m][o];
        out[((size_t)b * NN + n) * OUTC + o] = res;
    }
}

// ---------------------------------------------------------------------------
extern "C" void kernel_launch(void* const* d_in, const int* in_sizes, int n_in,
                              void* d_out, int out_size) {
    const float* x     = (const float*)d_in[0];  // [4096,17,512]
    const float* adj   = (const float*)d_in[1];  // [17,17]
    const float* c     = (const float*)d_in[2];  // [4096,1,512]
    const float* W_mod = (const float*)d_in[3];  // [512,1024]
    const float* b_mod = (const float*)d_in[4];  // [1024]
    const float* Wg    = (const float*)d_in[5];  // [3,512,3]
    const float* bg    = (const float*)d_in[6];  // [3]
    float* out = (float*)d_out;                  // [4096,17,3] f32

    lap_kernel<<<1, 320>>>(adj);
    dim3 g1((2 * DIM) / TN, BATCH / TM);         // (8, 64)
    mod_gemm<<<g1, 256>>>(c, W_mod, b_mod);
    final_kernel<<<BATCH, 192>>>(x, Wg, bg, out);
}

// round 4
// speedup vs baseline: 2.4277x; 2.4277x over previous
#include <cuda_runtime.h>
#include <cuda_bf16.h>
#include <cstdint>

#define BATCH 4096
#define NN 17
#define DIM 512
#define OUTC 3

// ----------------------------- device scratch ------------------------------
__device__ __align__(16) __nv_bfloat16 g_Ahi[(size_t)BATCH * DIM];   // silu(c) hi
__device__ __align__(16) __nv_bfloat16 g_Alo[(size_t)BATCH * DIM];   // silu(c) lo
__device__ __align__(16) __nv_bfloat16 g_Bhi[(size_t)DIM * DIM];     // W2^T hi  [n][k]
__device__ __align__(16) __nv_bfloat16 g_Blo[(size_t)DIM * DIM];     // W2^T lo
__device__ __align__(16) float g_scale[(size_t)BATCH * DIM];         // scale[b,c]
__device__ float g_P1T[9 * DIM];                       // P1^T [t][d]
__device__ float g_C3[9];                              // b_mod1 @ Wg
__device__ float g_T3[(size_t)BATCH * 9];              // term3[b,t]
__device__ float g_L[NN * NN];
__device__ float g_Q[NN * NN];

__device__ __forceinline__ float silu_f(float v) { return v / (1.f + __expf(-v)); }

__device__ __forceinline__ uint32_t lds_u32(const __nv_bfloat16* p) {
    return *reinterpret_cast<const uint32_t*>(p);
}

// bf16 mma.sync (baseline PTX, runs on tensor pipe as HMMA)
__device__ __forceinline__ void mma_bf16(float* c, const uint32_t* a, const uint32_t* b) {
    asm volatile(
        "mma.sync.aligned.m16n8k16.row.col.f32.bf16.bf16.f32 "
        "{%0,%1,%2,%3}, {%4,%5,%6,%7}, {%8,%9}, {%0,%1,%2,%3};"
        : "+f"(c[0]), "+f"(c[1]), "+f"(c[2]), "+f"(c[3])
        : "r"(a[0]), "r"(a[1]), "r"(a[2]), "r"(a[3]), "r"(b[0]), "r"(b[1]));
}

// ---------------------------------------------------------------------------
// setup: blocks 0..64 compute P1^T (+C3); block 65 computes L and Q
// ---------------------------------------------------------------------------
__global__ __launch_bounds__(256) void setup_kernel(const float* __restrict__ Wmod,
                                                    const float* __restrict__ bmod,
                                                    const float* __restrict__ Wg,
                                                    const float* __restrict__ adj) {
    const int tid = threadIdx.x;
    if (blockIdx.x == 65) {
        __shared__ float sD[NN];
        __shared__ float sL[NN * NN];
        if (tid < NN) {
            float s = 0.f;
            #pragma unroll
            for (int m = 0; m < NN; m++) s += adj[tid * NN + m];
            sD[tid] = rsqrtf(s);
        }
        __syncthreads();
        for (int i = tid; i < NN * NN; i += 256) {
            int n = i / NN, m = i % NN;
            float v = ((n == m) ? 1.f : 0.f) - sD[n] * adj[i] * sD[m];
            sL[i] = v; g_L[i] = v;
        }
        __syncthreads();
        for (int i = tid; i < NN * NN; i += 256) {
            int n = i / NN, m = i % NN;
            float s = 0.f;
            #pragma unroll
            for (int j = 0; j < NN; j++) s += sL[n * NN + j] * sL[j * NN + m];
            g_Q[i] = 2.f * s - ((n == m) ? 1.f : 0.f);
        }
        return;
    }
    __shared__ float sWgT[9][DIM];
    const int w = tid >> 5, l = tid & 31;
    for (int i = tid; i < 9 * DIM; i += 256) {
        int k = i / (DIM * 3), r = i % (DIM * 3), c = r / 3, o = r % 3;
        sWgT[k * 3 + o][c] = Wg[i];
    }
    __syncthreads();
    int d = blockIdx.x * 8 + w;
    if (d > DIM) return;
    float acc[9];
    #pragma unroll
    for (int t = 0; t < 9; t++) acc[t] = 0.f;
    #pragma unroll
    for (int j = 0; j < 4; j++) {
        int idx = j * 32 + l;
        float4 wv = (d < DIM)
            ? reinterpret_cast<const float4*>(Wmod + (size_t)d * 2 * DIM)[idx]
            : reinterpret_cast<const float4*>(bmod)[idx];
        #pragma unroll
        for (int t = 0; t < 9; t++) {
            float4 p = reinterpret_cast<const float4*>(sWgT[t])[idx];
            acc[t] += wv.x * p.x + wv.y * p.y + wv.z * p.z + wv.w * p.w;
        }
    }
    #pragma unroll
    for (int t = 0; t < 9; t++) {
        float a = acc[t];
        #pragma unroll
        for (int off = 16; off; off >>= 1) a += __shfl_xor_sync(0xffffffffu, a, off);
        if (l == 0) {
            if (d < DIM) g_P1T[t * DIM + d] = a;
            else         g_C3[t] = a;
        }
    }
}

// ---------------------------------------------------------------------------
// prep_a: silu(c) -> bf16 hi/lo split
// ---------------------------------------------------------------------------
__global__ __launch_bounds__(256) void prep_a(const float* __restrict__ cin) {
    int idx = blockIdx.x * 256 + threadIdx.x;                  // float4 index
    float4 v = reinterpret_cast<const float4*>(cin)[idx];
    float s[4] = { silu_f(v.x), silu_f(v.y), silu_f(v.z), silu_f(v.w) };
    union U { __nv_bfloat16 b[4]; uint2 u; } hi, lo;
    #pragma unroll
    for (int e = 0; e < 4; e++) {
        __nv_bfloat16 h = __float2bfloat16(s[e]);
        hi.b[e] = h;
        lo.b[e] = __float2bfloat16(s[e] - __bfloat162float(h));
    }
    reinterpret_cast<uint2*>(g_Ahi)[idx] = hi.u;
    reinterpret_cast<uint2*>(g_Alo)[idx] = lo.u;
}

// ---------------------------------------------------------------------------
// prep_w2t: W2^T[n,k] = W_mod[k, 512+n], bf16 hi/lo split (tiled transpose)
// ---------------------------------------------------------------------------
__global__ void prep_w2t(const float* __restrict__ Wmod) {
    __shared__ float tile[32][33];
    int tx = threadIdx.x, ty = threadIdx.y;
    int n0 = blockIdx.x * 32, k0 = blockIdx.y * 32;
    tile[ty][tx] = Wmod[(size_t)(k0 + ty) * (2 * DIM) + DIM + n0 + tx];
    __syncthreads();
    float v = tile[tx][ty];
    __nv_bfloat16 h = __float2bfloat16(v);
    size_t oi = (size_t)(n0 + ty) * DIM + k0 + tx;
    g_Bhi[oi] = h;
    g_Blo[oi] = __float2bfloat16(v - __bfloat162float(h));
}

// ---------------------------------------------------------------------------
// scale GEMM: scale[4096,512] = silu(c) @ W2 + b_mod2
// bf16 hi/lo split (3 mma passes), mma.sync.m16n8k16, CTA 128x64, 8 warps,
// K-chunks of 32, reg-prefetch double buffer. smem pitch 40 bf16 (80B) ->
// conflict-free 32-bit fragment loads.
// ---------------------------------------------------------------------------
#define SAP 40
#define A_BUF (128 * SAP)       // bf16 elems per A buffer
#define B_BUF (64 * SAP)
#define GSMEM ((2 * A_BUF * 2 + 2 * B_BUF * 2) * 2)   // bytes = 61440

__global__ __launch_bounds__(256) void scale_gemm(const float* __restrict__ bmod) {
    extern __shared__ __nv_bfloat16 sm[];
    __nv_bfloat16* sAhi = sm;                       // [2][128*40]
    __nv_bfloat16* sAlo = sm + 2 * A_BUF;
    __nv_bfloat16* sBhi = sm + 4 * A_BUF;           // [2][64*40]
    __nv_bfloat16* sBlo = sm + 4 * A_BUF + 2 * B_BUF;

    const int tid = threadIdx.x;
    const int wid = tid >> 5, l = tid & 31;
    const int wm = wid & 3, wn = wid >> 2;
    const int fr = l >> 2;              // 0..7
    const int fc = (l & 3) * 2;         // 0,2,4,6
    const int m0 = blockIdx.x * 128, n0 = blockIdx.y * 64;

    // per-thread global load slots
    const int ar0 = tid >> 1;                    // A: f = tid + i*256 -> row=f>>2? see below
    float acc[2][4][4];
    #pragma unroll
    for (int mt = 0; mt < 2; mt++)
        #pragma unroll
        for (int nt = 0; nt < 4; nt++)
            #pragma unroll
            for (int e = 0; e < 4; e++) acc[mt][nt][e] = 0.f;

    uint4 rAh[2], rAl[2], rBh, rBl;

    auto ldg_chunk = [&](int kc) {
        const int kbase = kc * 32;
        #pragma unroll
        for (int i = 0; i < 2; i++) {
            int f = tid + i * 256;               // 0..511
            int row = f >> 2, seg = f & 3;
            const __nv_bfloat16* pa = g_Ahi + (size_t)(m0 + row) * DIM + kbase + seg * 8;
            const __nv_bfloat16* pl = g_Alo + (size_t)(m0 + row) * DIM + kbase + seg * 8;
            rAh[i] = *reinterpret_cast<const uint4*>(pa);
            rAl[i] = *reinterpret_cast<const uint4*>(pl);
        }
        {
            int row = tid >> 2, seg = tid & 3;   // 64 rows x 4 segs = 256
            rBh = *reinterpret_cast<const uint4*>(g_Bhi + (size_t)(n0 + row) * DIM + kbase + seg * 8);
            rBl = *reinterpret_cast<const uint4*>(g_Blo + (size_t)(n0 + row) * DIM + kbase + seg * 8);
        }
    };
    auto sts_chunk = [&](int buf) {
        #pragma unroll
        for (int i = 0; i < 2; i++) {
            int f = tid + i * 256;
            int row = f >> 2, seg = f & 3;
            *reinterpret_cast<uint4*>(sAhi + buf * A_BUF + row * SAP + seg * 8) = rAh[i];
            *reinterpret_cast<uint4*>(sAlo + buf * A_BUF + row * SAP + seg * 8) = rAl[i];
        }
        {
            int row = tid >> 2, seg = tid & 3;
            *reinterpret_cast<uint4*>(sBhi + buf * B_BUF + row * SAP + seg * 8) = rBh;
            *reinterpret_cast<uint4*>(sBlo + buf * B_BUF + row * SAP + seg * 8) = rBl;
        }
    };

    ldg_chunk(0);
    sts_chunk(0);
    __syncthreads();

    for (int kc = 0; kc < 16; ++kc) {
        if (kc < 15) ldg_chunk(kc + 1);
        const int buf = kc & 1;
        const __nv_bfloat16* Ah = sAhi + buf * A_BUF;
        const __nv_bfloat16* Al = sAlo + buf * A_BUF;
        const __nv_bfloat16* Bh = sBhi + buf * B_BUF;
        const __nv_bfloat16* Bl = sBlo + buf * B_BUF;
        #pragma unroll
        for (int kk = 0; kk < 32; kk += 16) {
            uint32_t ah[2][4], al[2][4], bh[4][2], bl[4][2];
            #pragma unroll
            for (int mt = 0; mt < 2; mt++) {
                const __nv_bfloat16* pa = Ah + (wm * 32 + mt * 16 + fr) * SAP + kk + fc;
                const __nv_bfloat16* pl = Al + (wm * 32 + mt * 16 + fr) * SAP + kk + fc;
                ah[mt][0] = lds_u32(pa);
                ah[mt][1] = lds_u32(pa + 8 * SAP);
                ah[mt][2] = lds_u32(pa + 8);
                ah[mt][3] = lds_u32(pa + 8 * SAP + 8);
                al[mt][0] = lds_u32(pl);
                al[mt][1] = lds_u32(pl + 8 * SAP);
                al[mt][2] = lds_u32(pl + 8);
                al[mt][3] = lds_u32(pl + 8 * SAP + 8);
            }
            #pragma unroll
            for (int nt = 0; nt < 4; nt++) {
                const __nv_bfloat16* pb = Bh + (wn * 32 + nt * 8 + fr) * SAP + kk + fc;
                const __nv_bfloat16* pq = Bl + (wn * 32 + nt * 8 + fr) * SAP + kk + fc;
                bh[nt][0] = lds_u32(pb);
                bh[nt][1] = lds_u32(pb + 8);
                bl[nt][0] = lds_u32(pq);
                bl[nt][1] = lds_u32(pq + 8);
            }
            #pragma unroll
            for (int mt = 0; mt < 2; mt++)
                #pragma unroll
                for (int nt = 0; nt < 4; nt++) {
                    mma_bf16(acc[mt][nt], ah[mt], bh[nt]);
                    mma_bf16(acc[mt][nt], ah[mt], bl[nt]);
                    mma_bf16(acc[mt][nt], al[mt], bh[nt]);
                }
        }
        if (kc < 15) {
            __syncthreads();
            sts_chunk((kc + 1) & 1);
            __syncthreads();
        }
    }

    // epilogue: + b_mod2, write g_scale
    #pragma unroll
    for (int mt = 0; mt < 2; mt++) {
        int m = m0 + wm * 32 + mt * 16 + fr;
        #pragma unroll
        for (int nt = 0; nt < 4; nt++) {
            int n = n0 + wn * 32 + nt * 8 + fc;
            float2 bv = *reinterpret_cast<const float2*>(bmod + DIM + n);
            float2 v0 = make_float2(acc[mt][nt][0] + bv.x, acc[mt][nt][1] + bv.y);
            float2 v1 = make_float2(acc[mt][nt][2] + bv.x, acc[mt][nt][3] + bv.y);
            *reinterpret_cast<float2*>(g_scale + (size_t)m * DIM + n) = v0;
            *reinterpret_cast<float2*>(g_scale + (size_t)(m + 8) * DIM + n) = v1;
        }
    }
}

// ---------------------------------------------------------------------------
// t3: term3[b,t] = silu(c[b]) . P1T[t] + C3[t]    (warp per b)
// ---------------------------------------------------------------------------
__global__ __launch_bounds__(256) void t3_kernel(const float* __restrict__ cin) {
    __shared__ float sP[9][DIM];
    __shared__ float sC[9];
    const int tid = threadIdx.x, w = tid >> 5, l = tid & 31;
    for (int i = tid; i < 9 * DIM; i += 256) (&sP[0][0])[i] = g_P1T[i];
    if (tid < 9) sC[tid] = g_C3[tid];
    __syncthreads();
    const int b = blockIdx.x * 8 + w;
    float acc[9];
    #pragma unroll
    for (int t = 0; t < 9; t++) acc[t] = 0.f;
    const float4* cv = reinterpret_cast<const float4*>(cin + (size_t)b * DIM);
    #pragma unroll
    for (int j = 0; j < 4; j++) {
        float4 v = cv[j * 32 + l];
        float4 s = make_float4(silu_f(v.x), silu_f(v.y), silu_f(v.z), silu_f(v.w));
        #pragma unroll
        for (int t = 0; t < 9; t++) {
            float4 p = reinterpret_cast<const float4*>(sP[t])[j * 32 + l];
            acc[t] += s.x * p.x + s.y * p.y + s.z * p.z + s.w * p.w;
        }
    }
    #pragma unroll
    for (int t = 0; t < 9; t++) {
        float a = acc[t];
        #pragma unroll
        for (int off = 16; off; off >>= 1) a += __shfl_xor_sync(0xffffffffu, a, off);
        if (l == 0) g_T3[(size_t)b * 9 + t] = a + sC[t];
    }
}

// ---------------------------------------------------------------------------
// final: LN -> *(1+scale) -> project (9 dots) -> graph combine (+t3, +bg)
// 2 batch elems per block; 6 warps, 3 rows per warp
// ---------------------------------------------------------------------------
__global__ __launch_bounds__(192) void final_kernel(const float* __restrict__ x,
                                                    const float* __restrict__ Wg,
                                                    const float* __restrict__ bg,
                                                    float* __restrict__ out) {
    __shared__ float sWg[9][DIM];
    __shared__ float sMod[DIM];          // scale only
    __shared__ float sL[NN * NN];
    __shared__ float sQ[NN * NN];
    __shared__ float sY[3][NN][OUTC];
    __shared__ float sT3[9];

    const int tid = threadIdx.x;
    const int w = tid >> 5;
    const int l = tid & 31;

    for (int i = tid; i < 9 * DIM; i += 192) {
        int k = i / (DIM * 3), r = i % (DIM * 3), c = r / 3, o = r % 3;
        sWg[k * 3 + o][c] = Wg[i];
    }
    for (int i = tid; i < NN * NN; i += 192) { sL[i] = g_L[i]; sQ[i] = g_Q[i]; }
    __syncthreads();

    for (int bb = 0; bb < 2; ++bb) {
        const int b = blockIdx.x * 2 + bb;
        if (bb) __syncthreads();
        if (tid < 128)
            reinterpret_cast<float4*>(sMod)[tid] =
                reinterpret_cast<const float4*>(g_scale + (size_t)b * DIM)[tid];
        if (tid < 9) sT3[tid] = g_T3[(size_t)b * 9 + tid];
        __syncthreads();

        float4 xr[3][4];
        float mean[3], rstd[3];
        #pragma unroll
        for (int r = 0; r < 3; r++) {
            int n = w * 3 + r; if (n > NN - 1) n = NN - 1;
            const float4* xp = reinterpret_cast<const float4*>(x + ((size_t)b * NN + n) * DIM);
            float s = 0.f, s2 = 0.f;
            #pragma unroll
            for (int j = 0; j < 4; j++) {
                float4 v = xp[j * 32 + l];
                xr[r][j] = v;
                s  += v.x + v.y + v.z + v.w;
                s2 += v.x * v.x + v.y * v.y + v.z * v.z + v.w * v.w;
            }
            #pragma unroll
            for (int off = 16; off; off >>= 1) {
                s  += __shfl_xor_sync(0xffffffffu, s,  off);
                s2 += __shfl_xor_sync(0xffffffffu, s2, off);
            }
            float mu  = s * (1.f / DIM);
            float var = s2 * (1.f / DIM) - mu * mu;
            mean[r] = mu;
            rstd[r] = rsqrtf(var + 1e-6f);
        }

        float acc[3][9];
        #pragma unroll
        for (int r = 0; r < 3; r++)
            #pragma unroll
            for (int t = 0; t < 9; t++) acc[r][t] = 0.f;

        #pragma unroll
        for (int j = 0; j < 4; j++) {
            float4 sc = reinterpret_cast<const float4*>(sMod)[j * 32 + l];
            float4 wv[9];
            #pragma unroll
            for (int t = 0; t < 9; t++)
                wv[t] = reinterpret_cast<const float4*>(sWg[t])[j * 32 + l];
            #pragma unroll
            for (int r = 0; r < 3; r++) {
                float4 v = xr[r][j];
                float4 xm;
                xm.x = (v.x - mean[r]) * rstd[r] * (1.f + sc.x);
                xm.y = (v.y - mean[r]) * rstd[r] * (1.f + sc.y);
                xm.z = (v.z - mean[r]) * rstd[r] * (1.f + sc.z);
                xm.w = (v.w - mean[r]) * rstd[r] * (1.f + sc.w);
                #pragma unroll
                for (int t = 0; t < 9; t++)
                    acc[r][t] += xm.x * wv[t].x + xm.y * wv[t].y + xm.z * wv[t].z + xm.w * wv[t].w;
            }
        }

        #pragma unroll
        for (int r = 0; r < 3; r++) {
            int n = w * 3 + r;
            #pragma unroll
            for (int t = 0; t < 9; t++) {
                float a = acc[r][t];
                #pragma unroll
                for (int off = 16; off; off >>= 1) a += __shfl_xor_sync(0xffffffffu, a, off);
                if (l == 0 && n < NN) sY[t / 3][n][t % 3] = a;
            }
        }
        __syncthreads();

        if (tid < NN * OUTC) {
            int n = tid / OUTC, o = tid - n * OUTC;
            float t31 = sT3[3 + o], t32 = sT3[6 + o];
            float res = sY[0][n][o] + sT3[o] + bg[o];
            #pragma unroll
            for (int m = 0; m < NN; m++)
                res += sL[n * NN + m] * (sY[1][m][o] + t31)
                     + sQ[n * NN + m] * (sY[2][m][o] + t32);
            out[((size_t)b * NN + n) * OUTC + o] = res;
        }
    }
}

// ---------------------------------------------------------------------------
extern "C" void kernel_launch(void* const* d_in, const int* in_sizes, int n_in,
                              void* d_out, int out_size) {
    const float* x     = (const float*)d_in[0];  // [4096,17,512]
    const float* adj   = (const float*)d_in[1];  // [17,17]
    const float* c     = (const float*)d_in[2];  // [4096,1,512]
    const float* W_mod = (const float*)d_in[3];  // [512,1024]
    const float* b_mod = (const float*)d_in[4];  // [1024]
    const float* Wg    = (const float*)d_in[5];  // [3,512,3]
    const float* bg    = (const float*)d_in[6];  // [3]
    float* out = (float*)d_out;                  // [4096,17,3] f32

    cudaFuncSetAttribute(scale_gemm, cudaFuncAttributeMaxDynamicSharedMemorySize, GSMEM);

    setup_kernel<<<66, 256>>>(W_mod, b_mod, Wg, adj);
    prep_a<<<(BATCH * DIM / 4) / 256, 256>>>(c);
    prep_w2t<<<dim3(16, 16), dim3(32, 32)>>>(W_mod);
    scale_gemm<<<dim3(BATCH / 128, DIM / 64), 256, GSMEM>>>(b_mod);
    t3_kernel<<<BATCH / 8, 256>>>(c);
    final_kernel<<<BATCH / 2, 192>>>(x, Wg, bg, out);
}

// round 5
// speedup vs baseline: 2.5603x; 1.0546x over previous
#include <cuda_runtime.h>
#include <cuda_bf16.h>
#include <cstdint>

#define BATCH 4096
#define NN 17
#define DIM 512
#define OUTC 3
#define KP 1536   // packed K = [hi|lo|hi] x 512

// ----------------------------- device scratch ------------------------------
__device__ __align__(16) __nv_bfloat16 g_Ap[(size_t)BATCH * KP];  // [Ahi|Alo|Ahi]
__device__ __align__(16) __nv_bfloat16 g_Bp[(size_t)DIM * KP];    // [Bhi|Bhi|Blo] (B^T rows)
__device__ __align__(16) float g_scale[(size_t)BATCH * DIM];
__device__ float g_P1T[9 * DIM];
__device__ float g_C3[9];
__device__ float g_T3[(size_t)BATCH * 9];
__device__ float g_L[NN * NN];
__device__ float g_Q[NN * NN];

__device__ __forceinline__ float silu_f(float v) { return v / (1.f + __expf(-v)); }

__device__ __forceinline__ uint32_t smem_u32(const void* p) {
    uint32_t a;
    asm("{ .reg .u64 t; cvta.to.shared.u64 t, %1; cvt.u32.u64 %0, t; }" : "=r"(a) : "l"(p));
    return a;
}
__device__ __forceinline__ void cp16(uint32_t dst, const void* src) {
    asm volatile("cp.async.cg.shared.global [%0], [%1], 16;" :: "r"(dst), "l"(src));
}
#define CP_COMMIT() asm volatile("cp.async.commit_group;" ::: "memory")
#define CP_WAIT(n)  asm volatile("cp.async.wait_group %0;" :: "n"(n) : "memory")

__device__ __forceinline__ void ldmx4(uint32_t* r, uint32_t addr) {
    asm volatile("ldmatrix.sync.aligned.m8n8.x4.shared.b16 {%0,%1,%2,%3}, [%4];"
                 : "=r"(r[0]), "=r"(r[1]), "=r"(r[2]), "=r"(r[3]) : "r"(addr));
}
__device__ __forceinline__ void mma_bf16(float* c, const uint32_t* a, const uint32_t* b) {
    asm volatile(
        "mma.sync.aligned.m16n8k16.row.col.f32.bf16.bf16.f32 "
        "{%0,%1,%2,%3}, {%4,%5,%6,%7}, {%8,%9}, {%0,%1,%2,%3};"
        : "+f"(c[0]), "+f"(c[1]), "+f"(c[2]), "+f"(c[3])
        : "r"(a[0]), "r"(a[1]), "r"(a[2]), "r"(a[3]), "r"(b[0]), "r"(b[1]));
}

// ---------------------------------------------------------------------------
// setup: blocks 0..64 compute P1^T (+C3); block 65 computes L and Q
// ---------------------------------------------------------------------------
__global__ __launch_bounds__(256) void setup_kernel(const float* __restrict__ Wmod,
                                                    const float* __restrict__ bmod,
                                                    const float* __restrict__ Wg,
                                                    const float* __restrict__ adj) {
    const int tid = threadIdx.x;
    if (blockIdx.x == 65) {
        __shared__ float sD[NN];
        __shared__ float sL[NN * NN];
        if (tid < NN) {
            float s = 0.f;
            #pragma unroll
            for (int m = 0; m < NN; m++) s += adj[tid * NN + m];
            sD[tid] = rsqrtf(s);
        }
        __syncthreads();
        for (int i = tid; i < NN * NN; i += 256) {
            int n = i / NN, m = i % NN;
            float v = ((n == m) ? 1.f : 0.f) - sD[n] * adj[i] * sD[m];
            sL[i] = v; g_L[i] = v;
        }
        __syncthreads();
        for (int i = tid; i < NN * NN; i += 256) {
            int n = i / NN, m = i % NN;
            float s = 0.f;
            #pragma unroll
            for (int j = 0; j < NN; j++) s += sL[n * NN + j] * sL[j * NN + m];
            g_Q[i] = 2.f * s - ((n == m) ? 1.f : 0.f);
        }
        return;
    }
    __shared__ float sWgT[9][DIM];
    const int w = tid >> 5, l = tid & 31;
    for (int i = tid; i < 9 * DIM; i += 256) {
        int k = i / (DIM * 3), r = i % (DIM * 3), c = r / 3, o = r % 3;
        sWgT[k * 3 + o][c] = Wg[i];
    }
    __syncthreads();
    int d = blockIdx.x * 8 + w;
    if (d > DIM) return;
    float acc[9];
    #pragma unroll
    for (int t = 0; t < 9; t++) acc[t] = 0.f;
    #pragma unroll
    for (int j = 0; j < 4; j++) {
        int idx = j * 32 + l;
        float4 wv = (d < DIM)
            ? reinterpret_cast<const float4*>(Wmod + (size_t)d * 2 * DIM)[idx]
            : reinterpret_cast<const float4*>(bmod)[idx];
        #pragma unroll
        for (int t = 0; t < 9; t++) {
            float4 p = reinterpret_cast<const float4*>(sWgT[t])[idx];
            acc[t] += wv.x * p.x + wv.y * p.y + wv.z * p.z + wv.w * p.w;
        }
    }
    #pragma unroll
    for (int t = 0; t < 9; t++) {
        float a = acc[t];
        #pragma unroll
        for (int off = 16; off; off >>= 1) a += __shfl_xor_sync(0xffffffffu, a, off);
        if (l == 0) {
            if (d < DIM) g_P1T[t * DIM + d] = a;
            else         g_C3[t] = a;
        }
    }
}

// ---------------------------------------------------------------------------
// prep_c: fused silu(c) -> bf16 hi/lo packed A' write  +  t3 dot products
// one warp per batch element
// ---------------------------------------------------------------------------
__global__ __launch_bounds__(256) void prep_c(const float* __restrict__ cin) {
    __shared__ float sP[9][DIM];
    __shared__ float sC[9];
    const int tid = threadIdx.x, w = tid >> 5, l = tid & 31;
    for (int i = tid; i < 9 * DIM; i += 256) (&sP[0][0])[i] = g_P1T[i];
    if (tid < 9) sC[tid] = g_C3[tid];
    __syncthreads();
    const int b = blockIdx.x * 8 + w;
    float acc[9];
    #pragma unroll
    for (int t = 0; t < 9; t++) acc[t] = 0.f;
    const float4* cv = reinterpret_cast<const float4*>(cin + (size_t)b * DIM);
    __nv_bfloat16* ap = g_Ap + (size_t)b * KP;
    #pragma unroll
    for (int j = 0; j < 4; j++) {
        int idx = j * 32 + l;
        float4 v = cv[idx];
        float s[4] = { silu_f(v.x), silu_f(v.y), silu_f(v.z), silu_f(v.w) };
        union U { __nv_bfloat16 b[4]; uint2 u; } hi, lo;
        #pragma unroll
        for (int e = 0; e < 4; e++) {
            __nv_bfloat16 h = __float2bfloat16(s[e]);
            hi.b[e] = h;
            lo.b[e] = __float2bfloat16(s[e] - __bfloat162float(h));
        }
        int kb = idx * 4;
        *reinterpret_cast<uint2*>(ap + kb)        = hi.u;
        *reinterpret_cast<uint2*>(ap + 512 + kb)  = lo.u;
        *reinterpret_cast<uint2*>(ap + 1024 + kb) = hi.u;
        // t3 dots
        #pragma unroll
        for (int t = 0; t < 9; t++) {
            float4 p = reinterpret_cast<const float4*>(sP[t])[idx];
            acc[t] += s[0] * p.x + s[1] * p.y + s[2] * p.z + s[3] * p.w;
        }
    }
    #pragma unroll
    for (int t = 0; t < 9; t++) {
        float a = acc[t];
        #pragma unroll
        for (int off = 16; off; off >>= 1) a += __shfl_xor_sync(0xffffffffu, a, off);
        if (l == 0) g_T3[(size_t)b * 9 + t] = a + sC[t];
    }
}

// ---------------------------------------------------------------------------
// prep_w2t: B'[n][*] from W_mod[k, 512+n] (tiled transpose + hi/lo split)
// ---------------------------------------------------------------------------
__global__ void prep_w2t(const float* __restrict__ Wmod) {
    __shared__ float tile[32][33];
    int tx = threadIdx.x, ty = threadIdx.y;
    int n0 = blockIdx.x * 32, k0 = blockIdx.y * 32;
    tile[ty][tx] = Wmod[(size_t)(k0 + ty) * (2 * DIM) + DIM + n0 + tx];
    __syncthreads();
    float v = tile[tx][ty];
    __nv_bfloat16 h = __float2bfloat16(v);
    __nv_bfloat16 lo = __float2bfloat16(v - __bfloat162float(h));
    size_t base = (size_t)(n0 + ty) * KP + (k0 + tx);
    g_Bp[base]        = h;
    g_Bp[base + 512]  = h;
    g_Bp[base + 1024] = lo;
}

// ---------------------------------------------------------------------------
// scale GEMM: [4096,512] = A'[4096,1536] @ B'^T, bf16 mma.sync,
// cp.async 4-stage pipeline + ldmatrix + XOR swizzle.
// CTA tile 128x128, 8 warps (4m x 2n), warp tile 32x64. grid = (32, 4).
// ---------------------------------------------------------------------------
#define TM 128
#define TN 128
#define TK 64
#define NSTAGE 4
#define A_ST_B (TM * TK * 2)              // 16384 bytes
#define B_ST_B (TN * TK * 2)              // 16384 bytes
#define STAGE_B (A_ST_B + B_ST_B)         // 32768
#define GSMEM (STAGE_B * NSTAGE)          // 131072

__global__ __launch_bounds__(256, 1) void scale_gemm(const float* __restrict__ bmod) {
    extern __shared__ __align__(128) char sm[];
    const uint32_t sbase = smem_u32(sm);
    const int tid = threadIdx.x;
    const int wid = tid >> 5, l = tid & 31;
    const int wm = wid >> 1, wn = wid & 1;
    const int m0 = blockIdx.x * TM, n0 = blockIdx.y * TN;

    auto load_stage = [&](int st, int chunk) {
        uint32_t abase = sbase + st * STAGE_B;
        uint32_t bbase = abase + A_ST_B;
        int k0 = chunk * TK;
        #pragma unroll
        for (int i = 0; i < 4; i++) {                       // A: 1024 16B-chunks
            int id = tid + i * 256;
            int row = id >> 3, kc = id & 7;
            uint32_t dst = abase + row * 128 + ((kc ^ (row & 7)) << 4);
            cp16(dst, g_Ap + (size_t)(m0 + row) * KP + k0 + kc * 8);
        }
        #pragma unroll
        for (int i = 0; i < 4; i++) {                       // B: 1024 16B-chunks
            int id = tid + i * 256;
            int row = id >> 3, kc = id & 7;
            uint32_t dst = bbase + row * 128 + ((kc ^ (row & 7)) << 4);
            cp16(dst, g_Bp + (size_t)(n0 + row) * KP + k0 + kc * 8);
        }
    };

    float acc[2][8][4];
    #pragma unroll
    for (int mt = 0; mt < 2; mt++)
        #pragma unroll
        for (int nt = 0; nt < 8; nt++)
            #pragma unroll
            for (int e = 0; e < 4; e++) acc[mt][nt][e] = 0.f;

    #pragma unroll
    for (int s = 0; s < 3; s++) { load_stage(s, s); CP_COMMIT(); }

    const int NCHUNK = KP / TK;            // 24
    for (int it = 0; it < NCHUNK; ++it) {
        CP_WAIT(2);
        __syncthreads();
        if (it + 3 < NCHUNK) load_stage((it + 3) & 3, it + 3);
        CP_COMMIT();
        uint32_t abase = sbase + (it & 3) * STAGE_B;
        uint32_t bbase = abase + A_ST_B;
        #pragma unroll
        for (int kk = 0; kk < 4; kk++) {                    // k16 steps
            int kc0 = kk * 2 + (l >> 4);
            uint32_t a[2][4], b[4][4];
            #pragma unroll
            for (int mt = 0; mt < 2; mt++) {
                int row = wm * 32 + mt * 16 + (l & 15);
                ldmx4(a[mt], abase + row * 128 + ((kc0 ^ (row & 7)) << 4));
            }
            #pragma unroll
            for (int g = 0; g < 4; g++) {
                int row = wn * 64 + g * 16 + (l & 15);
                ldmx4(b[g], bbase + row * 128 + ((kc0 ^ (row & 7)) << 4));
            }
            #pragma unroll
            for (int mt = 0; mt < 2; mt++)
                #pragma unroll
                for (int g = 0; g < 4; g++) {
                    uint32_t b0[2] = { b[g][0], b[g][2] };
                    uint32_t b1[2] = { b[g][1], b[g][3] };
                    mma_bf16(acc[mt][2 * g],     a[mt], b0);
                    mma_bf16(acc[mt][2 * g + 1], a[mt], b1);
                }
        }
    }
    CP_WAIT(0);

    // epilogue: + b_mod2 -> g_scale
    const int fr = l >> 2, fc = (l & 3) * 2;
    #pragma unroll
    for (int mt = 0; mt < 2; mt++) {
        int m = m0 + wm * 32 + mt * 16 + fr;
        #pragma unroll
        for (int nt = 0; nt < 8; nt++) {
            int n = n0 + wn * 64 + nt * 8 + fc;
            float2 bv = *reinterpret_cast<const float2*>(bmod + DIM + n);
            float2 v0 = make_float2(acc[mt][nt][0] + bv.x, acc[mt][nt][1] + bv.y);
            float2 v1 = make_float2(acc[mt][nt][2] + bv.x, acc[mt][nt][3] + bv.y);
            *reinterpret_cast<float2*>(g_scale + (size_t)m * DIM + n) = v0;
            *reinterpret_cast<float2*>(g_scale + (size_t)(m + 8) * DIM + n) = v1;
        }
    }
}

// ---------------------------------------------------------------------------
// final: LN -> *(1+scale) -> project (9 dots) -> graph combine (+t3, +bg)
// 2 b per block; 6 warps x 3 rows; 3-step shuffle + 4-partial smem reduce
// ---------------------------------------------------------------------------
__global__ __launch_bounds__(192) void final_kernel(const float* __restrict__ x,
                                                    const float* __restrict__ Wg,
                                                    const float* __restrict__ bg,
                                                    float* __restrict__ out) {
    __shared__ float sWg[9][DIM];
    __shared__ float sMod[DIM];
    __shared__ float sL[NN * NN];
    __shared__ float sQ[NN * NN];
    __shared__ float sY4[3][NN][OUTC][4];
    __shared__ float sYs[3][NN][OUTC];
    __shared__ float sT3[9];

    const int tid = threadIdx.x;
    const int w = tid >> 5;
    const int l = tid & 31;

    for (int i = tid; i < 9 * DIM; i += 192) {
        int k = i / (DIM * 3), r = i % (DIM * 3), c = r / 3, o = r % 3;
        sWg[k * 3 + o][c] = Wg[i];
    }
    for (int i = tid; i < NN * NN; i += 192) { sL[i] = g_L[i]; sQ[i] = g_Q[i]; }
    __syncthreads();

    for (int bb = 0; bb < 2; ++bb) {
        const int b = blockIdx.x * 2 + bb;
        if (bb) __syncthreads();
        if (tid < 128)
            reinterpret_cast<float4*>(sMod)[tid] =
                reinterpret_cast<const float4*>(g_scale + (size_t)b * DIM)[tid];
        if (tid < 9) sT3[tid] = g_T3[(size_t)b * 9 + tid];
        __syncthreads();

        float4 xr[3][4];
        float mean[3], rstd[3];
        #pragma unroll
        for (int r = 0; r < 3; r++) {
            int n = w * 3 + r; if (n > NN - 1) n = NN - 1;
            const float4* xp = reinterpret_cast<const float4*>(x + ((size_t)b * NN + n) * DIM);
            float s = 0.f, s2 = 0.f;
            #pragma unroll
            for (int j = 0; j < 4; j++) {
                float4 v = xp[j * 32 + l];
                xr[r][j] = v;
                s  += v.x + v.y + v.z + v.w;
                s2 += v.x * v.x + v.y * v.y + v.z * v.z + v.w * v.w;
            }
            #pragma unroll
            for (int off = 16; off; off >>= 1) {
                s  += __shfl_xor_sync(0xffffffffu, s,  off);
                s2 += __shfl_xor_sync(0xffffffffu, s2, off);
            }
            float mu  = s * (1.f / DIM);
            float var = s2 * (1.f / DIM) - mu * mu;
            mean[r] = mu;
            rstd[r] = rsqrtf(var + 1e-6f);
        }

        float acc[3][9];
        #pragma unroll
        for (int r = 0; r < 3; r++)
            #pragma unroll
            for (int t = 0; t < 9; t++) acc[r][t] = 0.f;

        #pragma unroll
        for (int j = 0; j < 4; j++) {
            float4 sc = reinterpret_cast<const float4*>(sMod)[j * 32 + l];
            float4 wv[9];
            #pragma unroll
            for (int t = 0; t < 9; t++)
                wv[t] = reinterpret_cast<const float4*>(sWg[t])[j * 32 + l];
            #pragma unroll
            for (int r = 0; r < 3; r++) {
                float4 v = xr[r][j];
                float4 xm;
                xm.x = (v.x - mean[r]) * rstd[r] * (1.f + sc.x);
                xm.y = (v.y - mean[r]) * rstd[r] * (1.f + sc.y);
                xm.z = (v.z - mean[r]) * rstd[r] * (1.f + sc.z);
                xm.w = (v.w - mean[r]) * rstd[r] * (1.f + sc.w);
                #pragma unroll
                for (int t = 0; t < 9; t++)
                    acc[r][t] += xm.x * wv[t].x + xm.y * wv[t].y + xm.z * wv[t].z + xm.w * wv[t].w;
            }
        }

        // 3-step butterfly -> 4 partials per (row, t), lanes 0-3 write
        #pragma unroll
        for (int r = 0; r < 3; r++) {
            int n = w * 3 + r;
            #pragma unroll
            for (int t = 0; t < 9; t++) {
                float a = acc[r][t];
                a += __shfl_xor_sync(0xffffffffu, a, 16);
                a += __shfl_xor_sync(0xffffffffu, a, 8);
                a += __shfl_xor_sync(0xffffffffu, a, 4);
                if (l < 4 && n < NN) sY4[t / 3][n][t % 3][l] = a;
            }
        }
        __syncthreads();
        if (tid < 3 * NN * OUTC) {               // 153
            int k = tid / (NN * OUTC), r = tid % (NN * OUTC);
            int n = r / OUTC, o = r % OUTC;
            const float* p = sY4[k][n][o];
            sYs[k][n][o] = (p[0] + p[1]) + (p[2] + p[3]);
        }
        __syncthreads();

        if (tid < NN * OUTC) {
            int n = tid / OUTC, o = tid - n * OUTC;
            float t31 = sT3[3 + o], t32 = sT3[6 + o];
            float res = sYs[0][n][o] + sT3[o] + bg[o];
            #pragma unroll
            for (int m = 0; m < NN; m++)
                res += sL[n * NN + m] * (sYs[1][m][o] + t31)
                     + sQ[n * NN + m] * (sYs[2][m][o] + t32);
            out[((size_t)b * NN + n) * OUTC + o] = res;
        }
    }
}

// ---------------------------------------------------------------------------
extern "C" void kernel_launch(void* const* d_in, const int* in_sizes, int n_in,
                              void* d_out, int out_size) {
    const float* x     = (const float*)d_in[0];  // [4096,17,512]
    const float* adj   = (const float*)d_in[1];  // [17,17]
    const float* c     = (const float*)d_in[2];  // [4096,1,512]
    const float* W_mod = (const float*)d_in[3];  // [512,1024]
    const float* b_mod = (const float*)d_in[4];  // [1024]
    const float* Wg    = (const float*)d_in[5];  // [3,512,3]
    const float* bg    = (const float*)d_in[6];  // [3]
    float* out = (float*)d_out;                  // [4096,17,3] f32

    cudaFuncSetAttribute(scale_gemm, cudaFuncAttributeMaxDynamicSharedMemorySize, GSMEM);

    setup_kernel<<<66, 256>>>(W_mod, b_mod, Wg, adj);
    prep_w2t<<<dim3(16, 16), dim3(32, 32)>>>(W_mod);
    prep_c<<<BATCH / 8, 256>>>(c);
    scale_gemm<<<dim3(BATCH / TM, DIM / TN), 256, GSMEM>>>(b_mod);
    final_kernel<<<BATCH / 2, 192>>>(x, Wg, bg, out);
}